// round 7
// baseline (speedup 1.0000x reference)
#include <cuda_runtime.h>

typedef unsigned long long ull;

// ---------------- static device scratch (no allocations allowed) ----------------
__device__ float g_y[2048 * 384];           // conv outputs + bias, rows r = l*32+b
__device__ float g_h[2048 * 384];           // post-BN/leaky/mask features
__device__ float g_mean[384];
__device__ float g_rstd[384];
__device__ float g_a[32 * 64 * 128];        // (b,l,128): h @ w0[:C] + b0
__device__ float g_bb[32 * 64 * 128];       // (b,l,128): h @ w0[C:]
__device__ float g_pacc[4 * 2048 * 128];    // per-j-chunk partial sums
__device__ float g_q[2048 * 128];           // output-MLP hidden

__device__ __forceinline__ float lk(float x) { return x >= 0.f ? x : 0.1f * x; }

__device__ __forceinline__ void fma2(ull& acc, ull a, ull b) {
    asm("fma.rn.f32x2 %0,%1,%2,%0;" : "+l"(acc) : "l"(a), "l"(b));
}
__device__ __forceinline__ ull pack2(float x) {
    ull r; asm("mov.b64 %0,{%1,%1};" : "=l"(r) : "f"(x)); return r;
}
__device__ __forceinline__ float2 unpk(ull v) {
    float2 f; asm("mov.b64 {%0,%1},%2;" : "=f"(f.x), "=f"(f.y) : "l"(v)); return f;
}

// =====================================================================
// Kernel 1: both convolutions as shifted GEMMs (merged grid)
// GEMM: M=2048 (r=l*32+b), N=COUT, K=WIN*512; tile 64m x 32n, BK=32
// 256 threads, per-thread 4m x 2n via f32x2
// =====================================================================
template <int WIN>
__device__ __forceinline__ void conv_gemm(const float* __restrict__ x,
                                          const float* __restrict__ mask,
                                          const float* __restrict__ w,
                                          const float* __restrict__ bias,
                                          int bm0, int bn0, int coff,
                                          float* As, float* Bs) {
    constexpr int K = WIN * 512;
    const int t = threadIdx.x;
    const int tm = t >> 4, tn = t & 15;
    ull acc[4] = {0ULL, 0ULL, 0ULL, 0ULL};

    for (int k0 = 0; k0 < K; k0 += 32) {
        #pragma unroll
        for (int it = 0; it < 8; ++it) {
            int idx = t + it * 256;                // 0..2047
            int kk = idx & 31, mm = idx >> 5;
            int r = bm0 + mm, l = r >> 5, bq = r & 31;
            int kidx = k0 + kk;
            int e = kidx & 511;
            int lp = l + (kidx >> 9) - (WIN - 1) / 2;
            float v = 0.f;
            if (lp >= 0 && lp < 64) {
                int rb = lp * 32 + bq;
                v = x[rb * 512 + e] * mask[rb];
            }
            As[kk * 65 + mm] = v;
        }
        #pragma unroll
        for (int it = 0; it < 4; ++it) {
            int idx = t + it * 256;                // 0..1023
            int kk = idx & 31, nn = idx >> 5;
            Bs[kk * 34 + nn] = w[(bn0 + nn) * K + k0 + kk];
        }
        __syncthreads();
        #pragma unroll
        for (int kk = 0; kk < 32; ++kk) {
            ull wp = *(const ull*)(Bs + kk * 34 + tn * 2);
            #pragma unroll
            for (int i = 0; i < 4; ++i) {
                ull ap = pack2(As[kk * 65 + tm * 4 + i]);
                fma2(acc[i], ap, wp);
            }
        }
        __syncthreads();
    }
    float blo = bias[bn0 + tn * 2], bhi = bias[bn0 + tn * 2 + 1];
    #pragma unroll
    for (int i = 0; i < 4; ++i) {
        float2 f = unpk(acc[i]);
        int r = bm0 + tm * 4 + i;
        g_y[r * 384 + coff + bn0 + tn * 2]     = f.x + blo;
        g_y[r * 384 + coff + bn0 + tn * 2 + 1] = f.y + bhi;
    }
}

__global__ __launch_bounds__(256) void convs_kernel(const float* __restrict__ x,
                                                    const float* __restrict__ mask,
                                                    const float* __restrict__ cw0,
                                                    const float* __restrict__ cb0,
                                                    const float* __restrict__ cw1,
                                                    const float* __restrict__ cb1) {
    __shared__ float As[32 * 65];
    __shared__ float Bs[32 * 34];
    int bx = blockIdx.x;
    if (bx < 256) {   // conv0: 32 m-tiles x 8 n-tiles (COUT=256)
        conv_gemm<1>(x, mask, cw0, cb0, (bx >> 3) * 64, (bx & 7) * 32, 0, As, Bs);
    } else {          // conv1: 32 m-tiles x 4 n-tiles (COUT=128)
        int b2 = bx - 256;
        conv_gemm<3>(x, mask, cw1, cb1, (b2 >> 2) * 64, (b2 & 3) * 32, 256, As, Bs);
    }
}

// =====================================================================
// Kernel 2: per-channel batch stats (mean, biased var -> rstd)
// =====================================================================
__global__ __launch_bounds__(256) void stats_kernel() {
    const int c = blockIdx.x;
    const int t = threadIdx.x;
    float s = 0.f, s2 = 0.f;
    for (int r = t; r < 2048; r += 256) {
        float v = g_y[r * 384 + c];
        s += v; s2 += v * v;
    }
    __shared__ float ss[256], ss2[256];
    ss[t] = s; ss2[t] = s2;
    __syncthreads();
    for (int off = 128; off > 0; off >>= 1) {
        if (t < off) { ss[t] += ss[t + off]; ss2[t] += ss2[t + off]; }
        __syncthreads();
    }
    if (t == 0) {
        float m = ss[0] * (1.f / 2048.f);
        float var = ss2[0] * (1.f / 2048.f) - m * m;
        g_mean[c] = m;
        g_rstd[c] = rsqrtf(var + 1e-5f);
    }
}

// =====================================================================
// Kernel 3: BN apply + leaky + mask -> h
// =====================================================================
__global__ __launch_bounds__(256) void bn_kernel(const float* __restrict__ mask,
                                                 const float* __restrict__ gamma0,
                                                 const float* __restrict__ beta0,
                                                 const float* __restrict__ gamma1,
                                                 const float* __restrict__ beta1) {
    int idx = blockIdx.x * 256 + threadIdx.x;
    if (idx >= 2048 * 384) return;
    int r = idx / 384, c = idx - r * 384;
    float g  = (c < 256) ? gamma0[c] : gamma1[c - 256];
    float bt = (c < 256) ? beta0[c]  : beta1[c - 256];
    float v = (g_y[idx] - g_mean[c]) * g_rstd[c] * g + bt;
    g_h[idx] = lk(v) * mask[r];
}

// =====================================================================
// Kernel 4: a = h@w0[:C] + b0, bb = h@w0[C:]  (K=384, N=128 each)
// tile 64m x 32n, BK=32; output layout row = b*64 + l
// =====================================================================
__global__ __launch_bounds__(256) void ab_kernel(const float* __restrict__ w0,
                                                 const float* __restrict__ b0) {
    __shared__ float As[32 * 65];
    __shared__ float Bs[32 * 34];
    const int bm0 = blockIdx.x * 64, bn0 = blockIdx.y * 32;
    const int which = blockIdx.z;
    const int t = threadIdx.x, tm = t >> 4, tn = t & 15;
    ull acc[4] = {0ULL, 0ULL, 0ULL, 0ULL};

    for (int k0 = 0; k0 < 384; k0 += 32) {
        #pragma unroll
        for (int it = 0; it < 8; ++it) {
            int idx = t + it * 256;
            int kk = idx & 31, mm = idx >> 5;
            As[kk * 65 + mm] = g_h[(bm0 + mm) * 384 + k0 + kk];
        }
        #pragma unroll
        for (int it = 0; it < 4; ++it) {
            int idx = t + it * 256;
            int nn = idx & 31, kk = idx >> 5;
            Bs[kk * 34 + nn] = w0[(which * 384 + k0 + kk) * 128 + bn0 + nn];
        }
        __syncthreads();
        #pragma unroll
        for (int kk = 0; kk < 32; ++kk) {
            ull wp = *(const ull*)(Bs + kk * 34 + tn * 2);
            #pragma unroll
            for (int i = 0; i < 4; ++i) {
                ull ap = pack2(As[kk * 65 + tm * 4 + i]);
                fma2(acc[i], ap, wp);
            }
        }
        __syncthreads();
    }
    int c = bn0 + tn * 2;
    float blo = 0.f, bhi = 0.f;
    if (which == 0) { blo = b0[c]; bhi = b0[c + 1]; }   // fold b0 into a
    float* dst = which ? g_bb : g_a;
    #pragma unroll
    for (int i = 0; i < 4; ++i) {
        float2 f = unpk(acc[i]);
        int r = bm0 + tm * 4 + i;
        int l = r >> 5, bq = r & 31;
        dst[(bq * 64 + l) * 128 + c]     = f.x + blo;
        dst[(bq * 64 + l) * 128 + c + 1] = f.y + bhi;
    }
}

// =====================================================================
// Kernel 5: fused pairwise MLP (the hot loop)
// grid (32 b, 4 j-chunks), 256 threads, 229376 B dynamic smem.
// Warp w owns rows 8w..8w+7 end-to-end -> no block syncs in j-loop.
// =====================================================================
__global__ __launch_bounds__(256, 1) void pair_kernel(const float* __restrict__ w1,
                                                      const float* __restrict__ b1,
                                                      const float* __restrict__ w2,
                                                      const float* __restrict__ b2,
                                                      const float* __restrict__ w3,
                                                      const float* __restrict__ b3) {
    extern __shared__ float sm[];
    float* ws  = sm;                 // 3 x 128 x 128
    float* act = sm + 3 * 16384;     // 64 x 128 (in-place activations)

    const int t = threadIdx.x;
    const int b = blockIdx.x, jc = blockIdx.y;

    // stage all three weight matrices once
    {
        const float4* s1 = (const float4*)w1;
        const float4* s2 = (const float4*)w2;
        const float4* s3 = (const float4*)w3;
        float4* d1 = (float4*)ws;
        float4* d2 = (float4*)(ws + 16384);
        float4* d3 = (float4*)(ws + 32768);
        for (int i = t; i < 4096; i += 256) { d1[i] = s1[i]; d2[i] = s2[i]; d3[i] = s3[i]; }
    }
    __syncthreads();

    const int wid = t >> 5, lane = t & 31;
    const int m0 = wid * 8;
    const int col = lane * 4;

    float4 bias[3];
    bias[0] = *(const float4*)(b1 + col);
    bias[1] = *(const float4*)(b2 + col);
    bias[2] = *(const float4*)(b3 + col);

    // a rows for this warp, constant over j: register-cache
    float4 areg[8];
    #pragma unroll
    for (int r = 0; r < 8; ++r)
        areg[r] = *(const float4*)(g_a + (b * 64 + m0 + r) * 128 + col);

    float4 jacc[8];
    #pragma unroll
    for (int r = 0; r < 8; ++r) jacc[r] = make_float4(0.f, 0.f, 0.f, 0.f);

    for (int jj = 0; jj < 16; ++jj) {
        const int j = jc * 16 + jj;
        float4 bb4 = *(const float4*)(g_bb + (b * 64 + j) * 128 + col);

        // fill: act = leaky(a + bb)  (b0 folded into a)
        #pragma unroll
        for (int r = 0; r < 8; ++r) {
            float4 v;
            v.x = lk(areg[r].x + bb4.x);
            v.y = lk(areg[r].y + bb4.y);
            v.z = lk(areg[r].z + bb4.z);
            v.w = lk(areg[r].w + bb4.w);
            *(float4*)(act + (m0 + r) * 128 + col) = v;
        }
        __syncwarp();

        #pragma unroll
        for (int L = 0; L < 3; ++L) {
            const float* wl = ws + L * 16384;
            ull acc0[8], acc1[8];
            #pragma unroll
            for (int r = 0; r < 8; ++r) { acc0[r] = 0ULL; acc1[r] = 0ULL; }

            #pragma unroll 4
            for (int k = 0; k < 128; k += 4) {
                ulonglong2 wk0 = *(const ulonglong2*)(wl + (k + 0) * 128 + col);
                ulonglong2 wk1 = *(const ulonglong2*)(wl + (k + 1) * 128 + col);
                ulonglong2 wk2 = *(const ulonglong2*)(wl + (k + 2) * 128 + col);
                ulonglong2 wk3 = *(const ulonglong2*)(wl + (k + 3) * 128 + col);
                #pragma unroll
                for (int r = 0; r < 8; ++r) {
                    float4 av = *(const float4*)(act + (m0 + r) * 128 + k);
                    ull p0 = pack2(av.x), p1 = pack2(av.y);
                    ull p2 = pack2(av.z), p3 = pack2(av.w);
                    fma2(acc0[r], p0, wk0.x); fma2(acc1[r], p0, wk0.y);
                    fma2(acc0[r], p1, wk1.x); fma2(acc1[r], p1, wk1.y);
                    fma2(acc0[r], p2, wk2.x); fma2(acc1[r], p2, wk2.y);
                    fma2(acc0[r], p3, wk3.x); fma2(acc1[r], p3, wk3.y);
                }
            }
            __syncwarp();   // all lanes done reading act before overwrite

            #pragma unroll
            for (int r = 0; r < 8; ++r) {
                float2 lo = unpk(acc0[r]);
                float2 hi = unpk(acc1[r]);
                float4 v;
                v.x = lk(lo.x + bias[L].x);
                v.y = lk(lo.y + bias[L].y);
                v.z = lk(hi.x + bias[L].z);
                v.w = lk(hi.y + bias[L].w);
                if (L < 2) {
                    *(float4*)(act + (m0 + r) * 128 + col) = v;
                } else {
                    jacc[r].x += v.x; jacc[r].y += v.y;
                    jacc[r].z += v.z; jacc[r].w += v.w;
                }
            }
            if (L < 2) __syncwarp();  // writes visible before next layer reads
        }
    }

    #pragma unroll
    for (int r = 0; r < 8; ++r)
        *(float4*)(g_pacc + (jc * 2048 + b * 64 + m0 + r) * 128 + col) = jacc[r];
}

// =====================================================================
// Kernel 6: q = leaky( (mean_j p * mask_i) @ w4 + b4 )
// grid 32 (one b each), 98304 B dynamic smem
// =====================================================================
__global__ __launch_bounds__(256, 1) void qa_kernel(const float* __restrict__ mask,
                                                    const float* __restrict__ w4,
                                                    const float* __restrict__ b4) {
    extern __shared__ float sm[];
    float* ws  = sm;            // 128 x 128
    float* act = sm + 16384;    // 64 x 128
    const int t = threadIdx.x, b = blockIdx.x;

    for (int i = t; i < 4096; i += 256) ((float4*)ws)[i] = ((const float4*)w4)[i];
    __syncthreads();

    const int wid = t >> 5, lane = t & 31;
    const int m0 = wid * 8, col = lane * 4;
    float4 bias = *(const float4*)(b4 + col);

    #pragma unroll
    for (int r = 0; r < 8; ++r) {
        int i = m0 + r;
        int row = b * 64 + i;
        float mk = mask[i * 32 + b] * (1.f / 64.f);
        float4 s = make_float4(0.f, 0.f, 0.f, 0.f);
        #pragma unroll
        for (int cp = 0; cp < 4; ++cp) {
            float4 p = *(const float4*)(g_pacc + (cp * 2048 + row) * 128 + col);
            s.x += p.x; s.y += p.y; s.z += p.z; s.w += p.w;
        }
        s.x *= mk; s.y *= mk; s.z *= mk; s.w *= mk;
        *(float4*)(act + i * 128 + col) = s;
    }
    __syncwarp();

    ull acc0[8], acc1[8];
    #pragma unroll
    for (int r = 0; r < 8; ++r) { acc0[r] = 0ULL; acc1[r] = 0ULL; }
    #pragma unroll 4
    for (int k = 0; k < 128; k += 4) {
        ulonglong2 wk0 = *(const ulonglong2*)(ws + (k + 0) * 128 + col);
        ulonglong2 wk1 = *(const ulonglong2*)(ws + (k + 1) * 128 + col);
        ulonglong2 wk2 = *(const ulonglong2*)(ws + (k + 2) * 128 + col);
        ulonglong2 wk3 = *(const ulonglong2*)(ws + (k + 3) * 128 + col);
        #pragma unroll
        for (int r = 0; r < 8; ++r) {
            float4 av = *(const float4*)(act + (m0 + r) * 128 + k);
            ull p0 = pack2(av.x), p1 = pack2(av.y), p2 = pack2(av.z), p3 = pack2(av.w);
            fma2(acc0[r], p0, wk0.x); fma2(acc1[r], p0, wk0.y);
            fma2(acc0[r], p1, wk1.x); fma2(acc1[r], p1, wk1.y);
            fma2(acc0[r], p2, wk2.x); fma2(acc1[r], p2, wk2.y);
            fma2(acc0[r], p3, wk3.x); fma2(acc1[r], p3, wk3.y);
        }
    }
    #pragma unroll
    for (int r = 0; r < 8; ++r) {
        float2 lo = unpk(acc0[r]);
        float2 hi = unpk(acc1[r]);
        float4 v;
        v.x = lk(lo.x + bias.x);
        v.y = lk(lo.y + bias.y);
        v.z = lk(hi.x + bias.z);
        v.w = lk(hi.y + bias.w);
        *(float4*)(g_q + (b * 64 + m0 + r) * 128 + col) = v;
    }
}

// =====================================================================
// Kernel 7: out = leaky(q @ w5 + b5) * mask   (128 -> 512, tiled over n)
// grid (32 b, 4 n-tiles), 98304 B dynamic smem
// =====================================================================
__global__ __launch_bounds__(256, 1) void outb_kernel(const float* __restrict__ mask,
                                                      const float* __restrict__ w5,
                                                      const float* __restrict__ b5,
                                                      float* __restrict__ out) {
    extern __shared__ float sm[];
    float* ws  = sm;            // 128 x 128 slice of w5
    float* act = sm + 16384;    // 64 x 128
    const int t = threadIdx.x, b = blockIdx.x;
    const int n0 = blockIdx.y * 128;

    for (int i = t; i < 4096; i += 256) {
        int k = i >> 5, nq = i & 31;
        ((float4*)ws)[k * 32 + nq] = ((const float4*)(w5 + k * 512 + n0))[nq];
    }
    __syncthreads();

    const int wid = t >> 5, lane = t & 31;
    const int m0 = wid * 8, col = lane * 4;
    float4 bias = *(const float4*)(b5 + n0 + col);

    #pragma unroll
    for (int r = 0; r < 8; ++r) {
        int row = b * 64 + m0 + r;
        *(float4*)(act + (m0 + r) * 128 + col) = *(const float4*)(g_q + row * 128 + col);
    }
    __syncwarp();

    ull acc0[8], acc1[8];
    #pragma unroll
    for (int r = 0; r < 8; ++r) { acc0[r] = 0ULL; acc1[r] = 0ULL; }
    #pragma unroll 4
    for (int k = 0; k < 128; k += 4) {
        ulonglong2 wk0 = *(const ulonglong2*)(ws + (k + 0) * 128 + col);
        ulonglong2 wk1 = *(const ulonglong2*)(ws + (k + 1) * 128 + col);
        ulonglong2 wk2 = *(const ulonglong2*)(ws + (k + 2) * 128 + col);
        ulonglong2 wk3 = *(const ulonglong2*)(ws + (k + 3) * 128 + col);
        #pragma unroll
        for (int r = 0; r < 8; ++r) {
            float4 av = *(const float4*)(act + (m0 + r) * 128 + k);
            ull p0 = pack2(av.x), p1 = pack2(av.y), p2 = pack2(av.z), p3 = pack2(av.w);
            fma2(acc0[r], p0, wk0.x); fma2(acc1[r], p0, wk0.y);
            fma2(acc0[r], p1, wk1.x); fma2(acc1[r], p1, wk1.y);
            fma2(acc0[r], p2, wk2.x); fma2(acc1[r], p2, wk2.y);
            fma2(acc0[r], p3, wk3.x); fma2(acc1[r], p3, wk3.y);
        }
    }
    #pragma unroll
    for (int r = 0; r < 8; ++r) {
        int i = m0 + r;
        float mk = mask[i * 32 + b];
        float2 lo = unpk(acc0[r]);
        float2 hi = unpk(acc1[r]);
        float4 v;
        v.x = lk(lo.x + bias.x) * mk;
        v.y = lk(lo.y + bias.y) * mk;
        v.z = lk(hi.x + bias.z) * mk;
        v.w = lk(hi.y + bias.w) * mk;
        *(float4*)(out + (i * 32 + b) * 512 + n0 + col) = v;
    }
}

// =====================================================================
extern "C" void kernel_launch(void* const* d_in, const int* in_sizes, int n_in,
                              void* d_out, int out_size) {
    const float* x     = (const float*)d_in[0];
    const float* xmask = (const float*)d_in[1];
    const float* cw0   = (const float*)d_in[2];
    const float* cb0   = (const float*)d_in[3];
    const float* gam0  = (const float*)d_in[4];
    const float* bet0  = (const float*)d_in[5];
    const float* cw1   = (const float*)d_in[6];
    const float* cb1   = (const float*)d_in[7];
    const float* gam1  = (const float*)d_in[8];
    const float* bet1  = (const float*)d_in[9];
    const float* w0    = (const float*)d_in[10];
    const float* b0    = (const float*)d_in[11];
    const float* w1    = (const float*)d_in[12];
    const float* b1    = (const float*)d_in[13];
    const float* w2    = (const float*)d_in[14];
    const float* b2    = (const float*)d_in[15];
    const float* w3    = (const float*)d_in[16];
    const float* b3    = (const float*)d_in[17];
    const float* w4    = (const float*)d_in[18];
    const float* b4    = (const float*)d_in[19];
    const float* w5    = (const float*)d_in[20];
    const float* b5    = (const float*)d_in[21];
    float* out = (float*)d_out;

    cudaFuncSetAttribute(pair_kernel, cudaFuncAttributeMaxDynamicSharedMemorySize, 229376);
    cudaFuncSetAttribute(qa_kernel,   cudaFuncAttributeMaxDynamicSharedMemorySize, 98304);
    cudaFuncSetAttribute(outb_kernel, cudaFuncAttributeMaxDynamicSharedMemorySize, 98304);

    convs_kernel<<<384, 256>>>(x, xmask, cw0, cb0, cw1, cb1);
    stats_kernel<<<384, 256>>>();
    bn_kernel<<<(2048 * 384 + 255) / 256, 256>>>(xmask, gam0, bet0, gam1, bet1);
    ab_kernel<<<dim3(32, 4, 2), 256>>>(w0, b0);
    pair_kernel<<<dim3(32, 4), 256, 229376>>>(w1, b1, w2, b2, w3, b3);
    qa_kernel<<<32, 256, 98304>>>(xmask, w4, b4);
    outb_kernel<<<dim3(32, 4), 256, 98304>>>(xmask, w5, b5, out);
}

// round 8
// speedup vs baseline: 1.0038x; 1.0038x over previous
#include <cuda_runtime.h>

typedef unsigned long long ull;

// ---------------- static device scratch (no allocations allowed) ----------------
__device__ float g_y[2048 * 384];           // conv outputs + bias, rows r = l*32+b
__device__ float g_h[2048 * 384];           // post-BN/leaky/mask features
__device__ float g_mean[384];
__device__ float g_rstd[384];
__device__ float g_a[32 * 64 * 128];        // (b,l,128): h @ w0[:C] + b0
__device__ float g_bb[32 * 64 * 128];       // (b,l,128): h @ w0[C:]
__device__ float g_pacc[4 * 2048 * 128];    // per-j-chunk partial sums
__device__ float g_q[2048 * 128];           // output-MLP hidden

__device__ __forceinline__ float lk(float x) { return x >= 0.f ? x : 0.1f * x; }

__device__ __forceinline__ void fma2(ull& acc, ull a, ull b) {
    asm("fma.rn.f32x2 %0,%1,%2,%0;" : "+l"(acc) : "l"(a), "l"(b));
}
__device__ __forceinline__ ull pack2(float x) {
    ull r; asm("mov.b64 %0,{%1,%1};" : "=l"(r) : "f"(x)); return r;
}
__device__ __forceinline__ float2 unpk(ull v) {
    float2 f; asm("mov.b64 {%0,%1},%2;" : "=f"(f.x), "=f"(f.y) : "l"(v)); return f;
}

// =====================================================================
// Kernel 1: both convolutions as shifted GEMMs (merged grid)
// GEMM: M=2048 (r=l*32+b), N=COUT, K=WIN*512; tile 64m x 32n, BK=32
// 256 threads, per-thread 4m x 2n via f32x2
// =====================================================================
template <int WIN>
__device__ __forceinline__ void conv_gemm(const float* __restrict__ x,
                                          const float* __restrict__ mask,
                                          const float* __restrict__ w,
                                          const float* __restrict__ bias,
                                          int bm0, int bn0, int coff,
                                          float* As, float* Bs) {
    constexpr int K = WIN * 512;
    const int t = threadIdx.x;
    const int tm = t >> 4, tn = t & 15;
    ull acc[4] = {0ULL, 0ULL, 0ULL, 0ULL};

    for (int k0 = 0; k0 < K; k0 += 32) {
        #pragma unroll
        for (int it = 0; it < 8; ++it) {
            int idx = t + it * 256;                // 0..2047
            int kk = idx & 31, mm = idx >> 5;
            int r = bm0 + mm, l = r >> 5, bq = r & 31;
            int kidx = k0 + kk;
            int e = kidx & 511;
            int lp = l + (kidx >> 9) - (WIN - 1) / 2;
            float v = 0.f;
            if (lp >= 0 && lp < 64) {
                int rb = lp * 32 + bq;
                v = x[rb * 512 + e] * mask[rb];
            }
            As[kk * 65 + mm] = v;
        }
        #pragma unroll
        for (int it = 0; it < 4; ++it) {
            int idx = t + it * 256;                // 0..1023
            int kk = idx & 31, nn = idx >> 5;
            Bs[kk * 34 + nn] = w[(bn0 + nn) * K + k0 + kk];
        }
        __syncthreads();
        #pragma unroll
        for (int kk = 0; kk < 32; ++kk) {
            ull wp = *(const ull*)(Bs + kk * 34 + tn * 2);
            #pragma unroll
            for (int i = 0; i < 4; ++i) {
                ull ap = pack2(As[kk * 65 + tm * 4 + i]);
                fma2(acc[i], ap, wp);
            }
        }
        __syncthreads();
    }
    float blo = bias[bn0 + tn * 2], bhi = bias[bn0 + tn * 2 + 1];
    #pragma unroll
    for (int i = 0; i < 4; ++i) {
        float2 f = unpk(acc[i]);
        int r = bm0 + tm * 4 + i;
        g_y[r * 384 + coff + bn0 + tn * 2]     = f.x + blo;
        g_y[r * 384 + coff + bn0 + tn * 2 + 1] = f.y + bhi;
    }
}

__global__ __launch_bounds__(256) void convs_kernel(const float* __restrict__ x,
                                                    const float* __restrict__ mask,
                                                    const float* __restrict__ cw0,
                                                    const float* __restrict__ cb0,
                                                    const float* __restrict__ cw1,
                                                    const float* __restrict__ cb1) {
    __shared__ float As[32 * 65];
    __shared__ float Bs[32 * 34];
    int bx = blockIdx.x;
    if (bx < 256) {   // conv0: 32 m-tiles x 8 n-tiles (COUT=256)
        conv_gemm<1>(x, mask, cw0, cb0, (bx >> 3) * 64, (bx & 7) * 32, 0, As, Bs);
    } else {          // conv1: 32 m-tiles x 4 n-tiles (COUT=128)
        int b2 = bx - 256;
        conv_gemm<3>(x, mask, cw1, cb1, (b2 >> 2) * 64, (b2 & 3) * 32, 256, As, Bs);
    }
}

// =====================================================================
// Kernel 2: per-channel batch stats (mean, biased var -> rstd)
// =====================================================================
__global__ __launch_bounds__(256) void stats_kernel() {
    const int c = blockIdx.x;
    const int t = threadIdx.x;
    float s = 0.f, s2 = 0.f;
    for (int r = t; r < 2048; r += 256) {
        float v = g_y[r * 384 + c];
        s += v; s2 += v * v;
    }
    __shared__ float ss[256], ss2[256];
    ss[t] = s; ss2[t] = s2;
    __syncthreads();
    for (int off = 128; off > 0; off >>= 1) {
        if (t < off) { ss[t] += ss[t + off]; ss2[t] += ss2[t + off]; }
        __syncthreads();
    }
    if (t == 0) {
        float m = ss[0] * (1.f / 2048.f);
        float var = ss2[0] * (1.f / 2048.f) - m * m;
        g_mean[c] = m;
        g_rstd[c] = rsqrtf(var + 1e-5f);
    }
}

// =====================================================================
// Kernel 3: BN apply + leaky + mask -> h
// =====================================================================
__global__ __launch_bounds__(256) void bn_kernel(const float* __restrict__ mask,
                                                 const float* __restrict__ gamma0,
                                                 const float* __restrict__ beta0,
                                                 const float* __restrict__ gamma1,
                                                 const float* __restrict__ beta1) {
    int idx = blockIdx.x * 256 + threadIdx.x;
    if (idx >= 2048 * 384) return;
    int r = idx / 384, c = idx - r * 384;
    float g  = (c < 256) ? gamma0[c] : gamma1[c - 256];
    float bt = (c < 256) ? beta0[c]  : beta1[c - 256];
    float v = (g_y[idx] - g_mean[c]) * g_rstd[c] * g + bt;
    g_h[idx] = lk(v) * mask[r];
}

// =====================================================================
// Kernel 4: a = h@w0[:C] + b0, bb = h@w0[C:]  (K=384, N=128 each)
// tile 64m x 32n, BK=32; output layout row = b*64 + l
// =====================================================================
__global__ __launch_bounds__(256) void ab_kernel(const float* __restrict__ w0,
                                                 const float* __restrict__ b0) {
    __shared__ float As[32 * 65];
    __shared__ float Bs[32 * 34];
    const int bm0 = blockIdx.x * 64, bn0 = blockIdx.y * 32;
    const int which = blockIdx.z;
    const int t = threadIdx.x, tm = t >> 4, tn = t & 15;
    ull acc[4] = {0ULL, 0ULL, 0ULL, 0ULL};

    for (int k0 = 0; k0 < 384; k0 += 32) {
        #pragma unroll
        for (int it = 0; it < 8; ++it) {
            int idx = t + it * 256;
            int kk = idx & 31, mm = idx >> 5;
            As[kk * 65 + mm] = g_h[(bm0 + mm) * 384 + k0 + kk];
        }
        #pragma unroll
        for (int it = 0; it < 4; ++it) {
            int idx = t + it * 256;
            int nn = idx & 31, kk = idx >> 5;
            Bs[kk * 34 + nn] = w0[(which * 384 + k0 + kk) * 128 + bn0 + nn];
        }
        __syncthreads();
        #pragma unroll
        for (int kk = 0; kk < 32; ++kk) {
            ull wp = *(const ull*)(Bs + kk * 34 + tn * 2);
            #pragma unroll
            for (int i = 0; i < 4; ++i) {
                ull ap = pack2(As[kk * 65 + tm * 4 + i]);
                fma2(acc[i], ap, wp);
            }
        }
        __syncthreads();
    }
    int c = bn0 + tn * 2;
    float blo = 0.f, bhi = 0.f;
    if (which == 0) { blo = b0[c]; bhi = b0[c + 1]; }   // fold b0 into a
    float* dst = which ? g_bb : g_a;
    #pragma unroll
    for (int i = 0; i < 4; ++i) {
        float2 f = unpk(acc[i]);
        int r = bm0 + tm * 4 + i;
        int l = r >> 5, bq = r & 31;
        dst[(bq * 64 + l) * 128 + c]     = f.x + blo;
        dst[(bq * 64 + l) * 128 + c + 1] = f.y + bhi;
    }
}

// =====================================================================
// Kernel 5: fused pairwise MLP (the hot loop)
// grid (32 b, 4 j-chunks), 256 threads, 229376 B dynamic smem.
// Warp w owns rows 8w..8w+7 end-to-end -> no block syncs in j-loop.
// =====================================================================
__global__ __launch_bounds__(256, 1) void pair_kernel(const float* __restrict__ w1,
                                                      const float* __restrict__ b1,
                                                      const float* __restrict__ w2,
                                                      const float* __restrict__ b2,
                                                      const float* __restrict__ w3,
                                                      const float* __restrict__ b3) {
    extern __shared__ float sm[];
    float* ws  = sm;                 // 3 x 128 x 128
    float* act = sm + 3 * 16384;     // 64 x 128 (in-place activations)

    const int t = threadIdx.x;
    const int b = blockIdx.x, jc = blockIdx.y;

    // stage all three weight matrices once
    {
        const float4* s1 = (const float4*)w1;
        const float4* s2 = (const float4*)w2;
        const float4* s3 = (const float4*)w3;
        float4* d1 = (float4*)ws;
        float4* d2 = (float4*)(ws + 16384);
        float4* d3 = (float4*)(ws + 32768);
        for (int i = t; i < 4096; i += 256) { d1[i] = s1[i]; d2[i] = s2[i]; d3[i] = s3[i]; }
    }
    __syncthreads();

    const int wid = t >> 5, lane = t & 31;
    const int m0 = wid * 8;
    const int col = lane * 4;

    float4 bias[3];
    bias[0] = *(const float4*)(b1 + col);
    bias[1] = *(const float4*)(b2 + col);
    bias[2] = *(const float4*)(b3 + col);

    // a rows for this warp, constant over j: register-cache
    float4 areg[8];
    #pragma unroll
    for (int r = 0; r < 8; ++r)
        areg[r] = *(const float4*)(g_a + (b * 64 + m0 + r) * 128 + col);

    float4 jacc[8];
    #pragma unroll
    for (int r = 0; r < 8; ++r) jacc[r] = make_float4(0.f, 0.f, 0.f, 0.f);

    for (int jj = 0; jj < 16; ++jj) {
        const int j = jc * 16 + jj;
        float4 bb4 = *(const float4*)(g_bb + (b * 64 + j) * 128 + col);

        // fill: act = leaky(a + bb)  (b0 folded into a)
        #pragma unroll
        for (int r = 0; r < 8; ++r) {
            float4 v;
            v.x = lk(areg[r].x + bb4.x);
            v.y = lk(areg[r].y + bb4.y);
            v.z = lk(areg[r].z + bb4.z);
            v.w = lk(areg[r].w + bb4.w);
            *(float4*)(act + (m0 + r) * 128 + col) = v;
        }
        __syncwarp();

        #pragma unroll
        for (int L = 0; L < 3; ++L) {
            const float* wl = ws + L * 16384;
            ull acc0[8], acc1[8];
            #pragma unroll
            for (int r = 0; r < 8; ++r) { acc0[r] = 0ULL; acc1[r] = 0ULL; }

            #pragma unroll 4
            for (int k = 0; k < 128; k += 4) {
                ulonglong2 wk0 = *(const ulonglong2*)(wl + (k + 0) * 128 + col);
                ulonglong2 wk1 = *(const ulonglong2*)(wl + (k + 1) * 128 + col);
                ulonglong2 wk2 = *(const ulonglong2*)(wl + (k + 2) * 128 + col);
                ulonglong2 wk3 = *(const ulonglong2*)(wl + (k + 3) * 128 + col);
                #pragma unroll
                for (int r = 0; r < 8; ++r) {
                    float4 av = *(const float4*)(act + (m0 + r) * 128 + k);
                    ull p0 = pack2(av.x), p1 = pack2(av.y);
                    ull p2 = pack2(av.z), p3 = pack2(av.w);
                    fma2(acc0[r], p0, wk0.x); fma2(acc1[r], p0, wk0.y);
                    fma2(acc0[r], p1, wk1.x); fma2(acc1[r], p1, wk1.y);
                    fma2(acc0[r], p2, wk2.x); fma2(acc1[r], p2, wk2.y);
                    fma2(acc0[r], p3, wk3.x); fma2(acc1[r], p3, wk3.y);
                }
            }
            __syncwarp();   // all lanes done reading act before overwrite

            #pragma unroll
            for (int r = 0; r < 8; ++r) {
                float2 lo = unpk(acc0[r]);
                float2 hi = unpk(acc1[r]);
                float4 v;
                v.x = lk(lo.x + bias[L].x);
                v.y = lk(lo.y + bias[L].y);
                v.z = lk(hi.x + bias[L].z);
                v.w = lk(hi.y + bias[L].w);
                if (L < 2) {
                    *(float4*)(act + (m0 + r) * 128 + col) = v;
                } else {
                    jacc[r].x += v.x; jacc[r].y += v.y;
                    jacc[r].z += v.z; jacc[r].w += v.w;
                }
            }
            if (L < 2) __syncwarp();  // writes visible before next layer reads
        }
    }

    #pragma unroll
    for (int r = 0; r < 8; ++r)
        *(float4*)(g_pacc + (jc * 2048 + b * 64 + m0 + r) * 128 + col) = jacc[r];
}

// =====================================================================
// Kernel 6: q = leaky( (mean_j p * mask_i) @ w4 + b4 )
// grid 32 (one b each), 98304 B dynamic smem
// =====================================================================
__global__ __launch_bounds__(256, 1) void qa_kernel(const float* __restrict__ mask,
                                                    const float* __restrict__ w4,
                                                    const float* __restrict__ b4) {
    extern __shared__ float sm[];
    float* ws  = sm;            // 128 x 128
    float* act = sm + 16384;    // 64 x 128
    const int t = threadIdx.x, b = blockIdx.x;

    for (int i = t; i < 4096; i += 256) ((float4*)ws)[i] = ((const float4*)w4)[i];
    __syncthreads();

    const int wid = t >> 5, lane = t & 31;
    const int m0 = wid * 8, col = lane * 4;
    float4 bias = *(const float4*)(b4 + col);

    #pragma unroll
    for (int r = 0; r < 8; ++r) {
        int i = m0 + r;
        int row = b * 64 + i;
        float mk = mask[i * 32 + b] * (1.f / 64.f);
        float4 s = make_float4(0.f, 0.f, 0.f, 0.f);
        #pragma unroll
        for (int cp = 0; cp < 4; ++cp) {
            float4 p = *(const float4*)(g_pacc + (cp * 2048 + row) * 128 + col);
            s.x += p.x; s.y += p.y; s.z += p.z; s.w += p.w;
        }
        s.x *= mk; s.y *= mk; s.z *= mk; s.w *= mk;
        *(float4*)(act + i * 128 + col) = s;
    }
    __syncwarp();

    ull acc0[8], acc1[8];
    #pragma unroll
    for (int r = 0; r < 8; ++r) { acc0[r] = 0ULL; acc1[r] = 0ULL; }
    #pragma unroll 4
    for (int k = 0; k < 128; k += 4) {
        ulonglong2 wk0 = *(const ulonglong2*)(ws + (k + 0) * 128 + col);
        ulonglong2 wk1 = *(const ulonglong2*)(ws + (k + 1) * 128 + col);
        ulonglong2 wk2 = *(const ulonglong2*)(ws + (k + 2) * 128 + col);
        ulonglong2 wk3 = *(const ulonglong2*)(ws + (k + 3) * 128 + col);
        #pragma unroll
        for (int r = 0; r < 8; ++r) {
            float4 av = *(const float4*)(act + (m0 + r) * 128 + k);
            ull p0 = pack2(av.x), p1 = pack2(av.y), p2 = pack2(av.z), p3 = pack2(av.w);
            fma2(acc0[r], p0, wk0.x); fma2(acc1[r], p0, wk0.y);
            fma2(acc0[r], p1, wk1.x); fma2(acc1[r], p1, wk1.y);
            fma2(acc0[r], p2, wk2.x); fma2(acc1[r], p2, wk2.y);
            fma2(acc0[r], p3, wk3.x); fma2(acc1[r], p3, wk3.y);
        }
    }
    #pragma unroll
    for (int r = 0; r < 8; ++r) {
        float2 lo = unpk(acc0[r]);
        float2 hi = unpk(acc1[r]);
        float4 v;
        v.x = lk(lo.x + bias.x);
        v.y = lk(lo.y + bias.y);
        v.z = lk(hi.x + bias.z);
        v.w = lk(hi.y + bias.w);
        *(float4*)(g_q + (b * 64 + m0 + r) * 128 + col) = v;
    }
}

// =====================================================================
// Kernel 7: out = leaky(q @ w5 + b5) * mask   (128 -> 512, tiled over n)
// grid (32 b, 4 n-tiles), 98304 B dynamic smem
// =====================================================================
__global__ __launch_bounds__(256, 1) void outb_kernel(const float* __restrict__ mask,
                                                      const float* __restrict__ w5,
                                                      const float* __restrict__ b5,
                                                      float* __restrict__ out) {
    extern __shared__ float sm[];
    float* ws  = sm;            // 128 x 128 slice of w5
    float* act = sm + 16384;    // 64 x 128
    const int t = threadIdx.x, b = blockIdx.x;
    const int n0 = blockIdx.y * 128;

    for (int i = t; i < 4096; i += 256) {
        int k = i >> 5, nq = i & 31;
        ((float4*)ws)[k * 32 + nq] = ((const float4*)(w5 + k * 512 + n0))[nq];
    }
    __syncthreads();

    const int wid = t >> 5, lane = t & 31;
    const int m0 = wid * 8, col = lane * 4;
    float4 bias = *(const float4*)(b5 + n0 + col);

    #pragma unroll
    for (int r = 0; r < 8; ++r) {
        int row = b * 64 + m0 + r;
        *(float4*)(act + (m0 + r) * 128 + col) = *(const float4*)(g_q + row * 128 + col);
    }
    __syncwarp();

    ull acc0[8], acc1[8];
    #pragma unroll
    for (int r = 0; r < 8; ++r) { acc0[r] = 0ULL; acc1[r] = 0ULL; }
    #pragma unroll 4
    for (int k = 0; k < 128; k += 4) {
        ulonglong2 wk0 = *(const ulonglong2*)(ws + (k + 0) * 128 + col);
        ulonglong2 wk1 = *(const ulonglong2*)(ws + (k + 1) * 128 + col);
        ulonglong2 wk2 = *(const ulonglong2*)(ws + (k + 2) * 128 + col);
        ulonglong2 wk3 = *(const ulonglong2*)(ws + (k + 3) * 128 + col);
        #pragma unroll
        for (int r = 0; r < 8; ++r) {
            float4 av = *(const float4*)(act + (m0 + r) * 128 + k);
            ull p0 = pack2(av.x), p1 = pack2(av.y), p2 = pack2(av.z), p3 = pack2(av.w);
            fma2(acc0[r], p0, wk0.x); fma2(acc1[r], p0, wk0.y);
            fma2(acc0[r], p1, wk1.x); fma2(acc1[r], p1, wk1.y);
            fma2(acc0[r], p2, wk2.x); fma2(acc1[r], p2, wk2.y);
            fma2(acc0[r], p3, wk3.x); fma2(acc1[r], p3, wk3.y);
        }
    }
    #pragma unroll
    for (int r = 0; r < 8; ++r) {
        int i = m0 + r;
        float mk = mask[i * 32 + b];
        float2 lo = unpk(acc0[r]);
        float2 hi = unpk(acc1[r]);
        float4 v;
        v.x = lk(lo.x + bias.x) * mk;
        v.y = lk(lo.y + bias.y) * mk;
        v.z = lk(hi.x + bias.z) * mk;
        v.w = lk(hi.y + bias.w) * mk;
        *(float4*)(out + (i * 32 + b) * 512 + n0 + col) = v;
    }
}

// =====================================================================
extern "C" void kernel_launch(void* const* d_in, const int* in_sizes, int n_in,
                              void* d_out, int out_size) {
    const float* x     = (const float*)d_in[0];
    const float* xmask = (const float*)d_in[1];
    const float* cw0   = (const float*)d_in[2];
    const float* cb0   = (const float*)d_in[3];
    const float* gam0  = (const float*)d_in[4];
    const float* bet0  = (const float*)d_in[5];
    const float* cw1   = (const float*)d_in[6];
    const float* cb1   = (const float*)d_in[7];
    const float* gam1  = (const float*)d_in[8];
    const float* bet1  = (const float*)d_in[9];
    const float* w0    = (const float*)d_in[10];
    const float* b0    = (const float*)d_in[11];
    const float* w1    = (const float*)d_in[12];
    const float* b1    = (const float*)d_in[13];
    const float* w2    = (const float*)d_in[14];
    const float* b2    = (const float*)d_in[15];
    const float* w3    = (const float*)d_in[16];
    const float* b3    = (const float*)d_in[17];
    const float* w4    = (const float*)d_in[18];
    const float* b4    = (const float*)d_in[19];
    const float* w5    = (const float*)d_in[20];
    const float* b5    = (const float*)d_in[21];
    float* out = (float*)d_out;

    cudaFuncSetAttribute(pair_kernel, cudaFuncAttributeMaxDynamicSharedMemorySize, 229376);
    cudaFuncSetAttribute(qa_kernel,   cudaFuncAttributeMaxDynamicSharedMemorySize, 98304);
    cudaFuncSetAttribute(outb_kernel, cudaFuncAttributeMaxDynamicSharedMemorySize, 98304);

    convs_kernel<<<384, 256>>>(x, xmask, cw0, cb0, cw1, cb1);
    stats_kernel<<<384, 256>>>();
    bn_kernel<<<(2048 * 384 + 255) / 256, 256>>>(xmask, gam0, bet0, gam1, bet1);
    ab_kernel<<<dim3(32, 4, 2), 256>>>(w0, b0);
    pair_kernel<<<dim3(32, 4), 256, 229376>>>(w1, b1, w2, b2, w3, b3);
    qa_kernel<<<32, 256, 98304>>>(xmask, w4, b4);
    outb_kernel<<<dim3(32, 4), 256, 98304>>>(xmask, w5, b5, out);
}